// round 17
// baseline (speedup 1.0000x reference)
#include <cuda_runtime.h>
#include <cuda_fp16.h>
#include <cstdint>
#include <math.h>

// Problem constants
#define BB   4
#define SS   2048
#define DD   1024
#define HH   16
#define DHD  64
#define FFD  4096
#define ROWS (BB*SS)

// ---------------- scratch (device globals; no allocation allowed) ----------
__device__ __half g_xn_hi [(size_t)ROWS*DD];
__device__ __half g_qkv_hi[(size_t)ROWS*3*DD];
__device__ __half g_qkv_lo[(size_t)ROWS*3*DD];
__device__ __half g_att_hi[(size_t)ROWS*DD];
__device__ __half g_ctx_hi[(size_t)ROWS*DD];
__device__ __half g_h_hi  [(size_t)ROWS*DD];
__device__ __half g_ffh_hi[(size_t)ROWS*FFD];
// weight planes (hi only)
#define W_TOTAL ((size_t)16*1024*1024)
#define WOFF_ATTNIN  ((size_t)0)
#define WOFF_ATTNOUT ((size_t)3*1024*1024)
#define WOFF_INL     ((size_t)4*1024*1024)
#define WOFF_FF1     ((size_t)8*1024*1024)
#define WOFF_FF2     ((size_t)12*1024*1024)
__device__ __half g_w_hi[W_TOTAL];
__device__ float g_bcat[4*DD];
// fp32 intermediates
__device__ float g_x1 [(size_t)ROWS*DD];
__device__ float g_xs0[(size_t)ROWS*DD];
__device__ float g_inl[(size_t)ROWS*4*DD];
__device__ float g_x2 [(size_t)ROWS*DD];

// ---------------- helpers ---------------------------------------------------
__device__ __forceinline__ void wplane2(__half* hi, __half* lo,
                                        size_t idx, float v0, float v1)
{
    __half2 h = __floats2half2_rn(v0, v1);
    float2 hf = __half22float2(h);
    __half2 l = __floats2half2_rn(v0 - hf.x, v1 - hf.y);
    *reinterpret_cast<__half2*>(hi + idx) = h;
    *reinterpret_cast<__half2*>(lo + idx) = l;
}

__device__ __forceinline__ void whi2(__half* hi, size_t idx, float v0, float v1)
{
    __half2 h = __floats2half2_rn(v0, v1);
    *reinterpret_cast<__half2*>(hi + idx) = h;
}

__device__ __forceinline__ void hsplit2u(float x, float y,
                                         unsigned &h, unsigned &l)
{
    __half2 hb = __floats2half2_rn(x, y);
    float2 hf = __half22float2(hb);
    __half2 lb = __floats2half2_rn(x - hf.x, y - hf.y);
    h = *reinterpret_cast<unsigned*>(&hb);
    l = *reinterpret_cast<unsigned*>(&lb);
}

// ---------------- weight conversion (hi plane only) -------------------------
__global__ void __launch_bounds__(256) conv_w_k(
    const float* __restrict__ attn_in_w, const float* __restrict__ attn_out_w,
    const float* __restrict__ inl_u_w,   const float* __restrict__ inl_a_w,
    const float* __restrict__ inl_b_w,   const float* __restrict__ inl_g_w,
    const float* __restrict__ ff1_w,     const float* __restrict__ ff2_w)
{
    size_t e = ((size_t)blockIdx.x * 256 + threadIdx.x) * 2;
    const float* src;
    size_t off;
    if      (e < WOFF_ATTNOUT) { src = attn_in_w;  off = e - WOFF_ATTNIN; }
    else if (e < WOFF_INL)     { src = attn_out_w; off = e - WOFF_ATTNOUT; }
    else if (e < WOFF_INL + (size_t)1024*1024)   { src = inl_u_w; off = e - WOFF_INL; }
    else if (e < WOFF_INL + (size_t)2*1024*1024) { src = inl_a_w; off = e - WOFF_INL - (size_t)1024*1024; }
    else if (e < WOFF_INL + (size_t)3*1024*1024) { src = inl_b_w; off = e - WOFF_INL - (size_t)2*1024*1024; }
    else if (e < WOFF_FF1)     { src = inl_g_w; off = e - WOFF_INL - (size_t)3*1024*1024; }
    else if (e < WOFF_FF2)     { src = ff1_w;   off = e - WOFF_FF1; }
    else                       { src = ff2_w;   off = e - WOFF_FF2; }
    float2 v = *reinterpret_cast<const float2*>(src + off);
    __half2 h = __floats2half2_rn(v.x, v.y);
    *reinterpret_cast<__half2*>(g_w_hi + e) = h;
}

__global__ void bias_cat_k(const float* __restrict__ ub, const float* __restrict__ ab,
                           const float* __restrict__ bb, const float* __restrict__ gb)
{
    int i = blockIdx.x * 256 + threadIdx.x;
    int sel = i >> 10;
    int c = i & 1023;
    float v;
    if (sel == 0) v = ub[c];
    else if (sel == 1) v = ab[c];
    else if (sel == 2) v = bb[c];
    else v = gb[c];
    g_bcat[i] = v;
}

// ---------------- LayerNorm (fp32 out) --------------------------------------
__global__ void __launch_bounds__(256) layernorm_f(
    const float* __restrict__ x, const float* __restrict__ w,
    const float* __restrict__ b, float* __restrict__ y)
{
    int row = blockIdx.x;
    const float* xr = x + (size_t)row * DD;
    int tid = threadIdx.x;
    float4 v = *reinterpret_cast<const float4*>(xr + tid * 4);
    float s  = v.x + v.y + v.z + v.w;
    float ss = v.x*v.x + v.y*v.y + v.z*v.z + v.w*v.w;
    #pragma unroll
    for (int off = 16; off > 0; off >>= 1) {
        s  += __shfl_xor_sync(0xffffffffu, s,  off);
        ss += __shfl_xor_sync(0xffffffffu, ss, off);
    }
    __shared__ float sh_s[8];
    __shared__ float sh_ss[8];
    int wid = tid >> 5;
    int lane = tid & 31;
    if (lane == 0) { sh_s[wid] = s; sh_ss[wid] = ss; }
    __syncthreads();
    float ts = 0.f, tss = 0.f;
    #pragma unroll
    for (int i = 0; i < 8; i++) { ts += sh_s[i]; tss += sh_ss[i]; }
    float mu   = ts * (1.0f / DD);
    float var  = tss * (1.0f / DD) - mu * mu;
    float rstd = rsqrtf(var + 1e-5f);
    float4 wv = *reinterpret_cast<const float4*>(w + tid * 4);
    float4 bv = *reinterpret_cast<const float4*>(b + tid * 4);
    float4 o;
    o.x = (v.x - mu) * rstd * wv.x + bv.x;
    o.y = (v.y - mu) * rstd * wv.y + bv.y;
    o.z = (v.z - mu) * rstd * wv.z + bv.z;
    o.w = (v.w - mu) * rstd * wv.w + bv.w;
    *reinterpret_cast<float4*>(y + (size_t)row * DD + tid * 4) = o;
}

// ---------------- LayerNorm (fp16 hi plane out) ------------------------------
__global__ void __launch_bounds__(256) layernorm_h(
    const float* __restrict__ x, const float* __restrict__ w,
    const float* __restrict__ b, __half* __restrict__ yhi)
{
    int row = blockIdx.x;
    const float* xr = x + (size_t)row * DD;
    int tid = threadIdx.x;
    float4 v = *reinterpret_cast<const float4*>(xr + tid * 4);
    float s  = v.x + v.y + v.z + v.w;
    float ss = v.x*v.x + v.y*v.y + v.z*v.z + v.w*v.w;
    #pragma unroll
    for (int off = 16; off > 0; off >>= 1) {
        s  += __shfl_xor_sync(0xffffffffu, s,  off);
        ss += __shfl_xor_sync(0xffffffffu, ss, off);
    }
    __shared__ float sh_s[8];
    __shared__ float sh_ss[8];
    int wid = tid >> 5;
    int lane = tid & 31;
    if (lane == 0) { sh_s[wid] = s; sh_ss[wid] = ss; }
    __syncthreads();
    float ts = 0.f, tss = 0.f;
    #pragma unroll
    for (int i = 0; i < 8; i++) { ts += sh_s[i]; tss += sh_ss[i]; }
    float mu   = ts * (1.0f / DD);
    float var  = tss * (1.0f / DD) - mu * mu;
    float rstd = rsqrtf(var + 1e-5f);
    float4 wv = *reinterpret_cast<const float4*>(w + tid * 4);
    float4 bv = *reinterpret_cast<const float4*>(b + tid * 4);
    float o0 = (v.x - mu) * rstd * wv.x + bv.x;
    float o1 = (v.y - mu) * rstd * wv.y + bv.y;
    float o2 = (v.z - mu) * rstd * wv.z + bv.z;
    float o3 = (v.w - mu) * rstd * wv.w + bv.w;
    size_t base = (size_t)row * DD + tid * 4;
    whi2(yhi, base,     o0, o1);
    whi2(yhi, base + 2, o2, o3);
}

// ---------------- Fused INL integrator + LN2 (one block per row) ------------
__global__ void __launch_bounds__(256) inl_ln_k(
    const float* __restrict__ xs0, const float* __restrict__ inl,
    const float* __restrict__ x1,
    const float* __restrict__ w,  const float* __restrict__ b,
    float* __restrict__ x2, __half* __restrict__ h_hi)
{
    int row = blockIdx.x;
    int tid = threadIdx.x;
    size_t rbase = (size_t)row * DD + tid * 4;
    size_t ibase = (size_t)row * (size_t)(4*DD) + tid * 4;

    float4 xsv = *reinterpret_cast<const float4*>(xs0 + rbase);
    float4 uv  = *reinterpret_cast<const float4*>(inl + ibase);
    float4 av  = *reinterpret_cast<const float4*>(inl + ibase + DD);
    float4 bv4 = *reinterpret_cast<const float4*>(inl + ibase + 2*DD);
    float4 gv  = *reinterpret_cast<const float4*>(inl + ibase + 3*DD);
    float4 x1v = *reinterpret_cast<const float4*>(x1 + rbase);

    float xs[4] = {xsv.x, xsv.y, xsv.z, xsv.w};
    float uu[4] = {uv.x, uv.y, uv.z, uv.w};
    float aa[4] = {av.x, av.y, av.z, av.w};
    float bb[4] = {bv4.x, bv4.y, bv4.z, bv4.w};
    float gg[4] = {gv.x, gv.y, gv.z, gv.w};
    float x1a[4] = {x1v.x, x1v.y, x1v.z, x1v.w};
    float out[4];

    #pragma unroll
    for (int e = 0; e < 4; e++) {
        float alpha = 1.0f / (1.0f + expf(-aa[e]));
        float beta  = (bb[e] > 20.0f) ? bb[e] : log1pf(expf(bb[e]));
        float g     = 1.0f / (1.0f + expf(-gg[e]));
        float xv = xs[e];
        float vs = 0.0f;
        #pragma unroll
        for (int t = 0; t < 5; t++) {
            vs += 0.1f * (alpha * (0.0f - xv) - beta * vs + uu[e]);
            xv += 0.1f * g * vs;
        }
        out[e] = x1a[e] + xv;
    }
    *reinterpret_cast<float4*>(x2 + rbase) =
        make_float4(out[0], out[1], out[2], out[3]);

    float s  = out[0] + out[1] + out[2] + out[3];
    float ss = out[0]*out[0] + out[1]*out[1] + out[2]*out[2] + out[3]*out[3];
    #pragma unroll
    for (int off = 16; off > 0; off >>= 1) {
        s  += __shfl_xor_sync(0xffffffffu, s,  off);
        ss += __shfl_xor_sync(0xffffffffu, ss, off);
    }
    __shared__ float sh_s[8];
    __shared__ float sh_ss[8];
    int wid = tid >> 5;
    int lane = tid & 31;
    if (lane == 0) { sh_s[wid] = s; sh_ss[wid] = ss; }
    __syncthreads();
    float ts = 0.f, tss = 0.f;
    #pragma unroll
    for (int i = 0; i < 8; i++) { ts += sh_s[i]; tss += sh_ss[i]; }
    float mu   = ts * (1.0f / DD);
    float var  = tss * (1.0f / DD) - mu * mu;
    float rstd = rsqrtf(var + 1e-5f);
    float4 wv = *reinterpret_cast<const float4*>(w + tid * 4);
    float4 bv = *reinterpret_cast<const float4*>(b + tid * 4);
    float o0 = (out[0] - mu) * rstd * wv.x + bv.x;
    float o1 = (out[1] - mu) * rstd * wv.y + bv.y;
    float o2 = (out[2] - mu) * rstd * wv.z + bv.z;
    float o3 = (out[3] - mu) * rstd * wv.w + bv.w;
    whi2(h_hi, rbase,     o0, o1);
    whi2(h_hi, rbase + 2, o2, o3);
}

// ============================================================================
// asm wrappers
// ============================================================================
#define CP16(d, s) asm volatile("cp.async.cg.shared.global [%0], [%1], 16;\n" :: "r"(d), "l"(s))
#define CP_COMMIT() asm volatile("cp.async.commit_group;\n" ::)
#define CP_WAIT1() asm volatile("cp.async.wait_group 1;\n" ::)
#define CP_WAIT2() asm volatile("cp.async.wait_group 2;\n" ::)

__device__ __forceinline__ void ldsm4(unsigned &r0, unsigned &r1,
                                      unsigned &r2, unsigned &r3,
                                      unsigned addr)
{
    asm volatile(
        "ldmatrix.sync.aligned.m8n8.x4.shared.b16 {%0,%1,%2,%3}, [%4];\n"
        : "=r"(r0), "=r"(r1), "=r"(r2), "=r"(r3)
        : "r"(addr));
}

__device__ __forceinline__ void ldsm4t(unsigned &r0, unsigned &r1,
                                       unsigned &r2, unsigned &r3,
                                       unsigned addr)
{
    asm volatile(
        "ldmatrix.sync.aligned.m8n8.x4.trans.shared.b16 {%0,%1,%2,%3}, [%4];\n"
        : "=r"(r0), "=r"(r1), "=r"(r2), "=r"(r3)
        : "r"(addr));
}

__device__ __forceinline__ void mmaf16(float* c,
    unsigned a0, unsigned a1, unsigned a2, unsigned a3,
    unsigned b0, unsigned b1)
{
    asm volatile(
        "mma.sync.aligned.m16n8k16.row.col.f32.f16.f16.f32 "
        "{%0,%1,%2,%3}, {%4,%5,%6,%7}, {%8,%9}, {%0,%1,%2,%3};\n"
        : "+f"(c[0]), "+f"(c[1]), "+f"(c[2]), "+f"(c[3])
        : "r"(a0), "r"(a1), "r"(a2), "r"(a3), "r"(b0), "r"(b1));
}

// ============================================================================
// fp16 tensor-core GEMM: C[M,N] = Ahi @ Bhi[N,K]^T, fp32 accum.
// Block tile 128x128x32, 256 threads = 8 warps (2x4), warp tile 64x32.
// 4-stage cp.async (16KB/stage), single __syncthreads per k-tile,
// 2 CTAs/SM -> 16 warps/SM (occupancy-driven redesign).
// EPI: 0 fp32+bias; 1 hi(v+bias)+C2=res+v; 2 hi(GELU(v+bias));
//      3 fp32 v+bias+res; 4 hi+lo planes(v+bias).
// ============================================================================
#define STG_CHUNK 1024
#define GEM_STAGES 4
#define GEM_SMEM (GEM_STAGES * STG_CHUNK * 16)   // 65536

template<int EPI>
__global__ void __launch_bounds__(256, 2) gemm_f16(
    const __half* __restrict__ Ahi,
    const __half* __restrict__ Bhi,
    const float* __restrict__ bias, int M, int N, int K,
    float* __restrict__ C, const float* __restrict__ res, float* __restrict__ C2,
    __half* __restrict__ Chi, __half* __restrict__ Clo)
{
    extern __shared__ uint4 sm4[];
    const int tid  = threadIdx.x;
    const int lane = tid & 31;
    const int warp = tid >> 5;
    const int wm   = warp >> 2;     // 0..1 (64-row slab)
    const int wn   = warp & 3;      // 0..3 (32-col slab)
    const int bm   = blockIdx.y * 128;
    const int bn   = blockIdx.x * 128;

    const unsigned sbase =
        (unsigned)__cvta_generic_to_shared((void*)sm4);

    float acc[4][4][4];
    #pragma unroll
    for (int i = 0; i < 4; i++) {
        #pragma unroll
        for (int j = 0; j < 4; j++) {
            #pragma unroll
            for (int q = 0; q < 4; q++) acc[i][j][q] = 0.f;
        }
    }

    const int ar      = lane & 15;
    const int acolsel = lane >> 4;
    const int br      = (lane & 7) | ((lane >> 4) << 3);
    const int bcolsel = (lane >> 3) & 1;

    // ---- precomputed per-stage ldsm byte offsets ----
    unsigned aoff[2][4];
    unsigned boff[2][2];
    #pragma unroll
    for (int s = 0; s < 2; s++) {
        #pragma unroll
        for (int i = 0; i < 4; i++) {
            int row = wm * 64 + i * 16 + ar;
            int chunk = 2 * s + acolsel;
            int sw = chunk ^ ((row >> 1) & 3);
            aoff[s][i] = (unsigned)((row * 4 + sw) << 4);
        }
        #pragma unroll
        for (int p = 0; p < 2; p++) {
            int row = wn * 32 + p * 16 + br;
            int chunk = 2 * s + bcolsel;
            int sw = chunk ^ ((row >> 1) & 3);
            boff[s][p] = (unsigned)((512 + row * 4 + sw) << 4);
        }
    }

    const int nk = K / 32;

    // stage loader: 1024 chunks / 256 threads = 4 each.
    #define LOAD_STAGE(stg, kt_)                                                \
    {                                                                           \
        int k0 = (kt_) * 32;                                                    \
        _Pragma("unroll")                                                       \
        for (int it = 0; it < 4; it++) {                                        \
            int c   = tid + it * 256;                                           \
            int plane = c >> 9;                                                 \
            int rem = c & 511;                                                  \
            int row = rem >> 2;                                                 \
            int col = rem & 3;                                                  \
            int sw  = col ^ ((row >> 1) & 3);                                   \
            unsigned daddr = sbase +                                            \
                (unsigned)((((stg) * STG_CHUNK) + plane * 512 + row * 4 + sw) << 4); \
            const __half* gp;                                                   \
            size_t goff;                                                        \
            if (plane == 0) { gp = Ahi; goff = (size_t)(bm + row) * K + k0 + col * 8; } \
            else            { gp = Bhi; goff = (size_t)(bn + row) * K + k0 + col * 8; } \
            CP16(daddr, gp + goff);                                             \
        }                                                                       \
    }

    LOAD_STAGE(0, 0);
    CP_COMMIT();
    LOAD_STAGE(1, 1);
    CP_COMMIT();
    LOAD_STAGE(2, 2);
    CP_COMMIT();

    for (int kt = 0; kt < nk; kt++) {
        CP_WAIT2();
        __syncthreads();

        if (kt + 3 < nk) {
            LOAD_STAGE((kt + 3) & 3, kt + 3);
        }
        CP_COMMIT();

        const unsigned sb = sbase + (unsigned)(((kt & 3) * STG_CHUNK) << 4);

        #pragma unroll
        for (int s = 0; s < 2; s++) {
            unsigned a[4][4];
            #pragma unroll
            for (int i = 0; i < 4; i++) {
                ldsm4(a[i][0], a[i][1], a[i][2], a[i][3], sb + aoff[s][i]);
            }
            #pragma unroll
            for (int p = 0; p < 2; p++) {
                unsigned b0, b1, b2, b3;
                ldsm4(b0, b1, b2, b3, sb + boff[s][p]);
                #pragma unroll
                for (int i = 0; i < 4; i++) {
                    mmaf16(acc[i][2*p],
                           a[i][0], a[i][1], a[i][2], a[i][3], b0, b1);
                    mmaf16(acc[i][2*p+1],
                           a[i][0], a[i][1], a[i][2], a[i][3], b2, b3);
                }
            }
        }
    }
    #undef LOAD_STAGE

    const int rg = lane >> 2;
    const int q2 = (lane & 3) * 2;
    #pragma unroll
    for (int i = 0; i < 4; i++) {
        int r0 = bm + wm * 64 + i * 16 + rg;
        int r1 = r0 + 8;
        #pragma unroll
        for (int j = 0; j < 4; j++) {
            int col = bn + wn * 32 + j * 8 + q2;
            float b0 = bias[col];
            float b1 = bias[col + 1];
            float v0 = acc[i][j][0] + b0;
            float v1 = acc[i][j][1] + b1;
            float v2 = acc[i][j][2] + b0;
            float v3 = acc[i][j][3] + b1;
            size_t p0 = (size_t)r0 * N + col;
            size_t p1 = (size_t)r1 * N + col;
            if (EPI == 0) {
                C[p0] = v0; C[p0 + 1] = v1;
                C[p1] = v2; C[p1 + 1] = v3;
            }
            if (EPI == 1) {
                whi2(Chi, p0, v0, v1);
                whi2(Chi, p1, v2, v3);
                C2[p0]     = res[p0]     + v0;
                C2[p0 + 1] = res[p0 + 1] + v1;
                C2[p1]     = res[p1]     + v2;
                C2[p1 + 1] = res[p1 + 1] + v3;
            }
            if (EPI == 2) {
                v0 = 0.5f * v0 * (1.0f + erff(v0 * 0.70710678118654752f));
                v1 = 0.5f * v1 * (1.0f + erff(v1 * 0.70710678118654752f));
                v2 = 0.5f * v2 * (1.0f + erff(v2 * 0.70710678118654752f));
                v3 = 0.5f * v3 * (1.0f + erff(v3 * 0.70710678118654752f));
                whi2(Chi, p0, v0, v1);
                whi2(Chi, p1, v2, v3);
            }
            if (EPI == 3) {
                C[p0]     = v0 + res[p0];
                C[p0 + 1] = v1 + res[p0 + 1];
                C[p1]     = v2 + res[p1];
                C[p1 + 1] = v3 + res[p1 + 1];
            }
            if (EPI == 4) {
                wplane2(Chi, Clo, p0, v0, v1);
                wplane2(Chi, Clo, p1, v2, v3);
            }
        }
    }
}

// ============================================================================
// Tensor-core causal flash attention, fp16 2-term (Q,P split; K,V hi-only).
// ============================================================================
#define FA_SMEM (3072 * 16)   // 48 KB

__global__ void __launch_bounds__(128) flash_attn_tc(
    const __half* __restrict__ qhi, const __half* __restrict__ qlo,
    __half* __restrict__ outhi)
{
    extern __shared__ uint4 sm4[];
    const int tid  = threadIdx.x;
    const int lane = tid & 31;
    const int warp = tid >> 5;
    const int qt = blockIdx.x;
    const int h  = blockIdx.y;
    const int b  = blockIdx.z;
    const unsigned smem_base =
        (unsigned)__cvta_generic_to_shared((void*)sm4);

    const size_t rstr = 3 * DD;
    const size_t qrow0  = (size_t)b * SS + (size_t)qt * 64;
    const size_t kvrow0 = (size_t)b * SS;

    #pragma unroll
    for (int it = 0; it < 8; it++) {
        int c = tid + it * 128;
        int plane = c >> 9;
        int rem = c & 511;
        int row = rem >> 3;
        int ch  = rem & 7;
        int sw  = ch ^ (row & 7);
        unsigned d = smem_base + (unsigned)((plane * 512 + row * 8 + sw) << 4);
        const __half* src = (plane ? qlo : qhi);
        CP16(d, src + (qrow0 + row) * rstr + h * 64 + ch * 8);
    }
    CP_COMMIT();

    const int nkt = qt + 1;

    #define LOAD_KV(stg_, kt_)                                                  \
    {                                                                           \
        size_t krow = kvrow0 + (size_t)(kt_) * 64;                              \
        _Pragma("unroll")                                                       \
        for (int it = 0; it < 8; it++) {                                        \
            int c = tid + it * 128;                                             \
            int plane = c >> 9;   /* 0 Khi, 1 Vhi */                            \
            int rem = c & 511;                                                  \
            int row = rem >> 3;                                                 \
            int ch  = rem & 7;                                                  \
            int sw  = ch ^ (row & 7);                                           \
            unsigned d = smem_base +                                            \
                (unsigned)((1024 + (stg_) * 1024 + plane * 512 + row * 8 + sw) << 4); \
            size_t off = (krow + row) * rstr +                                  \
                         (plane ? 2 * DD : DD) + h * 64 + ch * 8;               \
            CP16(d, qhi + off);                                                 \
        }                                                                       \
    }

    LOAD_KV(0, 0);
    CP_COMMIT();
    if (nkt > 1) { LOAD_KV(1, 1); }
    CP_COMMIT();

    const int g = lane >> 2;
    const int q = lane & 3;

    float m0 = -INFINITY, m1 = -INFINITY;
    float l0 = 0.f, l1 = 0.f;
    float ov[8][4];
    #pragma unroll
    for (int j = 0; j < 8; j++) {
        #pragma unroll
        for (int k = 0; k < 4; k++) ov[j][k] = 0.f;
    }

    for (int kt = 0; kt < nkt; kt++) {
        CP_WAIT1();
        __syncthreads();
        const unsigned stg = smem_base +
            (unsigned)((1024 + (kt & 1) * 1024) << 4);

        float ss[8][4];
        #pragma unroll
        for (int j = 0; j < 8; j++) {
            #pragma unroll
            for (int k = 0; k < 4; k++) ss[j][k] = 0.f;
        }

        #pragma unroll
        for (int t = 0; t < 4; t++) {
            int arow = warp * 16 + (lane & 15);
            int ach  = 2 * t + (lane >> 4);
            int asw  = ach ^ (arow & 7);
            unsigned aaddr = smem_base + (unsigned)((arow * 8 + asw) << 4);
            unsigned qh0, qh1, qh2, qh3, ql0, ql1, ql2, ql3;
            ldsm4(qh0, qh1, qh2, qh3, aaddr);
            ldsm4(ql0, ql1, ql2, ql3, aaddr + (unsigned)(512 << 4));

            #pragma unroll
            for (int pb = 0; pb < 4; pb++) {
                int brow = pb * 16 + ((lane & 7) | ((lane >> 4) << 3));
                int bch  = 2 * t + ((lane >> 3) & 1);
                int bsw  = bch ^ (brow & 7);
                unsigned baddr = stg + (unsigned)((brow * 8 + bsw) << 4);
                unsigned kh0, kh1, kh2, kh3;
                ldsm4(kh0, kh1, kh2, kh3, baddr);
                mmaf16(ss[2*pb],   qh0, qh1, qh2, qh3, kh0, kh1);
                mmaf16(ss[2*pb],   ql0, ql1, ql2, ql3, kh0, kh1);
                mmaf16(ss[2*pb+1], qh0, qh1, qh2, qh3, kh2, kh3);
                mmaf16(ss[2*pb+1], ql0, ql1, ql2, ql3, kh2, kh3);
            }
        }

        #pragma unroll
        for (int j = 0; j < 8; j++) {
            ss[j][0] *= 0.125f; ss[j][1] *= 0.125f;
            ss[j][2] *= 0.125f; ss[j][3] *= 0.125f;
        }
        if (kt == qt) {
            int qr0 = warp * 16 + g;
            int qr1 = qr0 + 8;
            #pragma unroll
            for (int j = 0; j < 8; j++) {
                int k0 = 8 * j + 2 * q;
                int k1 = k0 + 1;
                if (k0 > qr0) ss[j][0] = -1e30f;
                if (k1 > qr0) ss[j][1] = -1e30f;
                if (k0 > qr1) ss[j][2] = -1e30f;
                if (k1 > qr1) ss[j][3] = -1e30f;
            }
        }

        float rm0 = -1e30f, rm1 = -1e30f;
        #pragma unroll
        for (int j = 0; j < 8; j++) {
            rm0 = fmaxf(rm0, fmaxf(ss[j][0], ss[j][1]));
            rm1 = fmaxf(rm1, fmaxf(ss[j][2], ss[j][3]));
        }
        rm0 = fmaxf(rm0, __shfl_xor_sync(0xffffffffu, rm0, 1));
        rm0 = fmaxf(rm0, __shfl_xor_sync(0xffffffffu, rm0, 2));
        rm1 = fmaxf(rm1, __shfl_xor_sync(0xffffffffu, rm1, 1));
        rm1 = fmaxf(rm1, __shfl_xor_sync(0xffffffffu, rm1, 2));
        float mn0 = fmaxf(m0, rm0);
        float mn1 = fmaxf(m1, rm1);
        float corr0 = __expf(m0 - mn0);
        float corr1 = __expf(m1 - mn1);
        m0 = mn0; m1 = mn1;

        float ps0 = 0.f, ps1 = 0.f;
        #pragma unroll
        for (int j = 0; j < 8; j++) {
            ss[j][0] = __expf(ss[j][0] - mn0);
            ss[j][1] = __expf(ss[j][1] - mn0);
            ss[j][2] = __expf(ss[j][2] - mn1);
            ss[j][3] = __expf(ss[j][3] - mn1);
            ps0 += ss[j][0] + ss[j][1];
            ps1 += ss[j][2] + ss[j][3];
        }
        ps0 += __shfl_xor_sync(0xffffffffu, ps0, 1);
        ps0 += __shfl_xor_sync(0xffffffffu, ps0, 2);
        ps1 += __shfl_xor_sync(0xffffffffu, ps1, 1);
        ps1 += __shfl_xor_sync(0xffffffffu, ps1, 2);
        l0 = l0 * corr0 + ps0;
        l1 = l1 * corr1 + ps1;
        #pragma unroll
        for (int j = 0; j < 8; j++) {
            ov[j][0] *= corr0; ov[j][1] *= corr0;
            ov[j][2] *= corr1; ov[j][3] *= corr1;
        }

        #pragma unroll
        for (int t = 0; t < 4; t++) {
            unsigned ph0, ph1, ph2, ph3, pl0, pl1, pl2, pl3;
            hsplit2u(ss[2*t][0],   ss[2*t][1],   ph0, pl0);
            hsplit2u(ss[2*t][2],   ss[2*t][3],   ph1, pl1);
            hsplit2u(ss[2*t+1][0], ss[2*t+1][1], ph2, pl2);
            hsplit2u(ss[2*t+1][2], ss[2*t+1][3], ph3, pl3);

            #pragma unroll
            for (int jd2 = 0; jd2 < 4; jd2++) {
                int vrow = 16 * t + (lane & 7) + ((lane >> 3) & 1) * 8;
                int vch  = jd2 * 2 + (lane >> 4);
                int vsw  = vch ^ (vrow & 7);
                unsigned vaddr = stg + (unsigned)((512 + vrow * 8 + vsw) << 4);
                unsigned vh0, vh1, vh2, vh3;
                ldsm4t(vh0, vh1, vh2, vh3, vaddr);
                mmaf16(ov[2*jd2],   ph0, ph1, ph2, ph3, vh0, vh1);
                mmaf16(ov[2*jd2],   pl0, pl1, pl2, pl3, vh0, vh1);
                mmaf16(ov[2*jd2+1], ph0, ph1, ph2, ph3, vh2, vh3);
                mmaf16(ov[2*jd2+1], pl0, pl1, pl2, pl3, vh2, vh3);
            }
        }

        __syncthreads();
        if (kt + 2 < nkt) { LOAD_KV(kt & 1, kt + 2); }
        CP_COMMIT();
    }
    #undef LOAD_KV

    float invl0 = 1.0f / l0;
    float invl1 = 1.0f / l1;
    #pragma unroll
    for (int jd = 0; jd < 8; jd++) {
        size_t p0 = (qrow0 + warp * 16 + g) * DD + h * 64 + 8 * jd + 2 * q;
        size_t p1 = p0 + (size_t)8 * DD;
        whi2(outhi, p0, ov[jd][0] * invl0, ov[jd][1] * invl0);
        whi2(outhi, p1, ov[jd][2] * invl1, ov[jd][3] * invl1);
    }
}

// ---------------- launch ----------------------------------------------------
extern "C" void kernel_launch(void* const* d_in, const int* in_sizes, int n_in,
                              void* d_out, int out_size)
{
    const float* x          = (const float*)d_in[0];
    const float* ln_attn_w  = (const float*)d_in[1];
    const float* ln_attn_b  = (const float*)d_in[2];
    const float* attn_in_w  = (const float*)d_in[3];
    const float* attn_in_b  = (const float*)d_in[4];
    const float* attn_out_w = (const float*)d_in[5];
    const float* attn_out_b = (const float*)d_in[6];
    const float* ln1_w      = (const float*)d_in[7];
    const float* ln1_b      = (const float*)d_in[8];
    const float* ln2_w      = (const float*)d_in[9];
    const float* ln2_b      = (const float*)d_in[10];
    const float* inl_u_w    = (const float*)d_in[11];
    const float* inl_u_b    = (const float*)d_in[12];
    const float* inl_a_w    = (const float*)d_in[13];
    const float* inl_a_b    = (const float*)d_in[14];
    const float* inl_b_w    = (const float*)d_in[15];
    const float* inl_b_b    = (const float*)d_in[16];
    const float* inl_g_w    = (const float*)d_in[17];
    const float* inl_g_b    = (const float*)d_in[18];
    const float* ff1_w      = (const float*)d_in[19];
    const float* ff1_b      = (const float*)d_in[20];
    const float* ff2_w      = (const float*)d_in[21];
    const float* ff2_b      = (const float*)d_in[22];
    float* out = (float*)d_out;

    __half *xn_hi = 0, *qkv_hi = 0, *qkv_lo = 0, *att_hi = 0;
    __half *ctx_hi = 0, *h_hi = 0, *ffh_hi = 0, *w_hi = 0;
    float *x1 = 0, *xs0 = 0, *inl = 0, *x2 = 0, *bcat = 0;
    cudaGetSymbolAddress((void**)&xn_hi,  g_xn_hi);
    cudaGetSymbolAddress((void**)&qkv_hi, g_qkv_hi);
    cudaGetSymbolAddress((void**)&qkv_lo, g_qkv_lo);
    cudaGetSymbolAddress((void**)&att_hi, g_att_hi);
    cudaGetSymbolAddress((void**)&ctx_hi, g_ctx_hi);
    cudaGetSymbolAddress((void**)&h_hi,   g_h_hi);
    cudaGetSymbolAddress((void**)&ffh_hi, g_ffh_hi);
    cudaGetSymbolAddress((void**)&w_hi,   g_w_hi);
    cudaGetSymbolAddress((void**)&x1,     g_x1);
    cudaGetSymbolAddress((void**)&xs0,    g_xs0);
    cudaGetSymbolAddress((void**)&inl,    g_inl);
    cudaGetSymbolAddress((void**)&x2,     g_x2);
    cudaGetSymbolAddress((void**)&bcat,   g_bcat);

    cudaFuncSetAttribute(gemm_f16<0>,
        cudaFuncAttributeMaxDynamicSharedMemorySize, GEM_SMEM);
    cudaFuncSetAttribute(gemm_f16<1>,
        cudaFuncAttributeMaxDynamicSharedMemorySize, GEM_SMEM);
    cudaFuncSetAttribute(gemm_f16<2>,
        cudaFuncAttributeMaxDynamicSharedMemorySize, GEM_SMEM);
    cudaFuncSetAttribute(gemm_f16<3>,
        cudaFuncAttributeMaxDynamicSharedMemorySize, GEM_SMEM);
    cudaFuncSetAttribute(gemm_f16<4>,
        cudaFuncAttributeMaxDynamicSharedMemorySize, GEM_SMEM);
    cudaFuncSetAttribute(flash_attn_tc,
        cudaFuncAttributeMaxDynamicSharedMemorySize, FA_SMEM);

    // 0) weight plane conversion + bias concat
    conv_w_k<<<(int)(W_TOTAL / 512), 256>>>(
        attn_in_w, attn_out_w, inl_u_w, inl_a_w, inl_b_w, inl_g_w, ff1_w, ff2_w);
    bias_cat_k<<<16, 256>>>(inl_u_b, inl_a_b, inl_b_b, inl_g_b);

    // 1) pre-attn LN -> xn hi plane
    layernorm_h<<<ROWS, 256>>>(x, ln_attn_w, ln_attn_b, xn_hi);

    // 2) QKV projection -> qkv hi+lo planes
    gemm_f16<4><<<dim3(3*DD/128, ROWS/128), 256, GEM_SMEM>>>(
        xn_hi, w_hi + WOFF_ATTNIN,
        attn_in_b, ROWS, 3*DD, DD, (float*)0, (const float*)0, (float*)0,
        qkv_hi, qkv_lo);

    // 3) tensor-core causal flash attention -> att hi plane
    flash_attn_tc<<<dim3(SS/64, HH, BB), 128, FA_SMEM>>>(
        qkv_hi, qkv_lo, att_hi);

    // 4) out-projection: ctx hi = proj+bias, x1 = x + proj+bias
    gemm_f16<1><<<dim3(DD/128, ROWS/128), 256, GEM_SMEM>>>(
        att_hi, w_hi + WOFF_ATTNOUT,
        attn_out_b, ROWS, DD, DD, (float*)0, x, x1, ctx_hi, (__half*)0);

    // 5) LN1(x1) -> xs0 fp32
    layernorm_f<<<ROWS, 256>>>(x1, ln1_w, ln1_b, xs0);

    // 6) fused INL controller projections: [ROWS, 4096] fp32
    gemm_f16<0><<<dim3(4*DD/128, ROWS/128), 256, GEM_SMEM>>>(
        ctx_hi, w_hi + WOFF_INL,
        bcat, ROWS, 4*DD, DD, inl, (const float*)0, (float*)0,
        (__half*)0, (__half*)0);

    // 7+8) fused INL dynamics + LN2 -> x2 (fp32) and h hi plane
    inl_ln_k<<<ROWS, 256>>>(xs0, inl, x1, ln2_w, ln2_b, x2, h_hi);

    // 9) FF1 + exact GELU -> ffh hi plane
    gemm_f16<2><<<dim3(FFD/128, ROWS/128), 256, GEM_SMEM>>>(
        h_hi, w_hi + WOFF_FF1,
        ff1_b, ROWS, FFD, DD, (float*)0, (const float*)0, (float*)0,
        ffh_hi, (__half*)0);

    // 10) FF2 + bias + residual -> out
    gemm_f16<3><<<dim3(DD/128, ROWS/128), 256, GEM_SMEM>>>(
        ffh_hi, w_hi + WOFF_FF2,
        ff2_b, ROWS, DD, FFD, out, x2, (float*)0,
        (__half*)0, (__half*)0);
}